// round 15
// baseline (speedup 1.0000x reference)
#include <cuda_runtime.h>
#include <cstdint>

// LIF layer scan: B=64, F=512, L=1024. rows = B*F = 32768.
// Output: z history then s history, each rows*L floats.
//
// Chunked scan: CH=4 chunks of 256 steps/row; chunks>0 warm up WUP=32 steps
// from v=0 (alpha^32 ~ 2e-5; spikes reset v to exactly 0 -> exact resync).
//
// Warp-specialized blocks (64 threads = 2 warps, 32 rows):
//   warp 0 (producer): cp.async loads (2 tiles ahead) + sequential scan,
//                      z written in place into the input stage.
//   warp 1 (store):    computes s from z sign and streams tile i-1 to gmem,
//                      fully overlapped with warp 0's scan of tile i.
// NSTG=4 stages so {scan i, store i-1, landed i+1, filling i+2} are all
// distinct (mod 4). One __syncthreads per tile provides the cross-warp
// ordering: the stage cp.async refills at iter i held tile i-2, whose store
// completed during iter i-1.
//
// smem 18.4KB/block -> 12 blocks/SM (24 warps). Row stride 36 floats
// (144B = 9*16: 16B-aligned cp.async dsts, conflict-free float4 LDS/STS).
// FFMA scan: vp = fmaf(alpha,v,omal*i), z = fmaf(beta,vp,-beta*thr).

#define L_DIM 1024
#define BR    32                 // rows per block
#define NTHR  64                 // 2 warps
#define TT    32                 // time-tile width
#define CH    4                  // chunks per row
#define CHL   (L_DIM / CH)       // 256 steps per chunk
#define WUP   32                 // warmup steps for chunks > 0
#define MT    (CHL / TT)         // 8 main tiles
#define WT    (WUP / TT)         // 1 warmup tile
#define NSTG  4                  // pipeline stages
#define STRD  36                 // smem row stride (floats)

__device__ __forceinline__ void cp_async16(uint32_t smem_dst, const void* gsrc) {
    asm volatile("cp.async.cg.shared.global [%0], [%1], 16;\n"
                 :: "r"(smem_dst), "l"(gsrc));
}
__device__ __forceinline__ void cp_commit() {
    asm volatile("cp.async.commit_group;\n");
}
template <int N>
__device__ __forceinline__ void cp_wait() {
    asm volatile("cp.async.wait_group %0;\n" :: "n"(N));
}

__device__ __forceinline__ float spike_of(float z) {
    // s = (z >= 0) ? 1.0f : 0.0f via sign bit (z == -0 cannot occur here)
    int zb = __float_as_int(z);
    return __int_as_float(0x3f800000 & ~(zb >> 31));
}

__global__ __launch_bounds__(NTHR) void lif_kernel(const float* __restrict__ I,
                                                   float* __restrict__ Z,
                                                   float* __restrict__ S) {
    __shared__ __align__(16) float sI[NSTG][BR][STRD];

    const int tid     = threadIdx.x;
    const int lane    = tid & 31;
    const int isStore = tid >> 5;                   // warp 1 = store warp

    const int chunk    = blockIdx.x & (CH - 1);
    const int rowBlk   = blockIdx.x >> 2;           // CH == 4
    const long rowBase = (long)rowBlk * BR;

    const int startT    = chunk * CHL - (chunk ? WUP : 0);
    const int numTiles  = chunk ? (WT + MT) : MT;
    const int storeFrom = chunk ? WT : 0;

    // alpha = float(exp(-DT/TAU)) = float(exp(-1/3))
    const float alpha = 0.71653131057378925043f;
    const float omal  = 1.0f - alpha;
    const float thr   = 0.25f;
    const float beta  = 10.0f;
    const float nbt   = -beta * thr;     // -2.5f

    float v = 0.0f;

    const long chunkBase = rowBase * L_DIM + startT;

    // Tile slice mapping (both warps): e4 = k*32 + lane ; r = e4/8 ;
    // c4 = (e4%8)*4 -> 8 consecutive lanes cover a row's 128B (full line).

    if (!isStore) {
        // ---- prologue: issue tiles 0 and 1 into stages 0,1 ----
        #pragma unroll
        for (int p = 0; p < 2; ++p) {
            const float* gb = I + chunkBase + p * TT;
            #pragma unroll
            for (int k = 0; k < 8; ++k) {
                int e4 = k * BR + lane;
                int r  = e4 >> 3;
                int c4 = (e4 & 7) << 2;
                uint32_t dst = (uint32_t)__cvta_generic_to_shared(&sI[p][r][c4]);
                cp_async16(dst, gb + (long)r * L_DIM + c4);
            }
            cp_commit();
        }
    }

    #pragma unroll 1
    for (int tile = 0; tile < numTiles; ++tile) {
        // Cross-warp invariant at this barrier: warp1 has completed stores of
        // all tiles <= tile-2, so stage (tile+2)&3 (which held tile-2) is free
        // for refill, and stage (tile-1)&3 holds warp0's scanned z of tile-1.
        __syncthreads();

        if (!isStore) {
            const long gbase = chunkBase + (long)tile * TT;

            if (tile + 2 < numTiles) {
                // ---- issue tile+2 into stage (tile+2)&3 ----
                const int  nxt = (tile + 2) & (NSTG - 1);
                const float* gb = I + gbase + 2 * TT;
                #pragma unroll
                for (int k = 0; k < 8; ++k) {
                    int e4 = k * BR + lane;
                    int r  = e4 >> 3;
                    int c4 = (e4 & 7) << 2;
                    uint32_t dst = (uint32_t)__cvta_generic_to_shared(&sI[nxt][r][c4]);
                    cp_async16(dst, gb + (long)r * L_DIM + c4);
                }
                cp_commit();
                cp_wait<2>();           // 3 pending after commit; oldest (tile) landed
            } else if (tile + 1 < numTiles) {
                cp_wait<1>();
            } else {
                cp_wait<0>();
            }
            __syncwarp();

            const int cur = tile & (NSTG - 1);
            const bool doStore = (tile >= storeFrom);

            // ---- sequential scan of TT steps; z written back in place ----
            #pragma unroll
            for (int c = 0; c < TT; c += 4) {
                float4 i4 = *reinterpret_cast<const float4*>(&sI[cur][lane][c]);
                float4 z4;
                float vp;
                vp = fmaf(alpha, v, __fmul_rn(omal, i4.x));
                z4.x = fmaf(beta, vp, nbt);
                v = (vp >= thr) ? 0.0f : vp;
                vp = fmaf(alpha, v, __fmul_rn(omal, i4.y));
                z4.y = fmaf(beta, vp, nbt);
                v = (vp >= thr) ? 0.0f : vp;
                vp = fmaf(alpha, v, __fmul_rn(omal, i4.z));
                z4.z = fmaf(beta, vp, nbt);
                v = (vp >= thr) ? 0.0f : vp;
                vp = fmaf(alpha, v, __fmul_rn(omal, i4.w));
                z4.w = fmaf(beta, vp, nbt);
                v = (vp >= thr) ? 0.0f : vp;
                if (doStore)
                    *reinterpret_cast<float4*>(&sI[cur][lane][c]) = z4;
            }
        } else {
            // ---- store warp: stream tile-1 (scanned last iteration) ----
            const int j = tile - 1;
            if (j >= storeFrom) {
                const int  stg    = j & (NSTG - 1);
                const long gbaseJ = chunkBase + (long)j * TT;
                #pragma unroll
                for (int k = 0; k < 8; ++k) {
                    int e4 = k * BR + lane;
                    int r  = e4 >> 3;
                    int c4 = (e4 & 7) << 2;
                    float4 z4 = *reinterpret_cast<const float4*>(&sI[stg][r][c4]);
                    float4 s4;
                    s4.x = spike_of(z4.x);
                    s4.y = spike_of(z4.y);
                    s4.z = spike_of(z4.z);
                    s4.w = spike_of(z4.w);
                    long g = gbaseJ + (long)r * L_DIM + c4;
                    __stcs(reinterpret_cast<float4*>(&Z[g]), z4);
                    __stcs(reinterpret_cast<float4*>(&S[g]), s4);
                }
            }
        }
    }

    // ---- epilogue: store the final tile ----
    __syncthreads();
    if (isStore) {
        const int  j      = numTiles - 1;
        const int  stg    = j & (NSTG - 1);
        const long gbaseJ = chunkBase + (long)j * TT;
        #pragma unroll
        for (int k = 0; k < 8; ++k) {
            int e4 = k * BR + lane;
            int r  = e4 >> 3;
            int c4 = (e4 & 7) << 2;
            float4 z4 = *reinterpret_cast<const float4*>(&sI[stg][r][c4]);
            float4 s4;
            s4.x = spike_of(z4.x);
            s4.y = spike_of(z4.y);
            s4.z = spike_of(z4.z);
            s4.w = spike_of(z4.w);
            long g = gbaseJ + (long)r * L_DIM + c4;
            __stcs(reinterpret_cast<float4*>(&Z[g]), z4);
            __stcs(reinterpret_cast<float4*>(&S[g]), s4);
        }
    }
}

extern "C" void kernel_launch(void* const* d_in, const int* in_sizes, int n_in,
                              void* d_out, int out_size) {
    const float* I = (const float*)d_in[0];
    float* out = (float*)d_out;
    const int n    = in_sizes[0];        // B*F*L = 33554432
    const int rows = n / L_DIM;          // 32768
    float* Z = out;                      // z history first
    float* S = out + n;                  // then s history
    lif_kernel<<<(rows / BR) * CH, NTHR>>>(I, Z, S);
}

// round 16
// speedup vs baseline: 1.0254x; 1.0254x over previous
#include <cuda_runtime.h>
#include <cstdint>

// LIF layer scan: B=64, F=512, L=1024. rows = B*F = 32768.
// Output: z history then s history, each rows*L floats.
//
// Chunked scan: CH=4 chunks of 256 steps/row; chunks>0 warm up WUP=32 steps
// from v=0 (alpha^32 ~ 2e-5; spikes reset v to exactly 0 -> exact resync).
//
// Warp-specialized blocks (64 threads = 2 warps, 32 rows):
//   warp 0 (producer): cp.async loads (2 tiles ahead) + sequential scan,
//                      z written in place into the input stage.
//   warp 1 (store):    computes s from z sign and streams tile i-1 to gmem,
//                      fully overlapped with warp 0's scan of tile i.
// NSTG=4 stages so {scan i, store i-1, landed i+1, filling i+2} are all
// distinct (mod 4). One __syncthreads per tile gives cross-warp ordering.
//
// smem 18.4KB/block -> 12 blocks/SM (24 warps). Row stride 36 floats
// (144B = 9*16: 16B-aligned cp.async dsts, conflict-free float4 LDS/STS).
// FFMA scan: vp = fmaf(alpha,v,omal*i), z = fmaf(beta,vp,-beta*thr).
//
// This round (write-path only): Z-tile burst then S-tile burst (no per-k
// interleaving of the two streams), plain .wb stores instead of .cs.

#define L_DIM 1024
#define BR    32                 // rows per block
#define NTHR  64                 // 2 warps
#define TT    32                 // time-tile width
#define CH    4                  // chunks per row
#define CHL   (L_DIM / CH)       // 256 steps per chunk
#define WUP   32                 // warmup steps for chunks > 0
#define MT    (CHL / TT)         // 8 main tiles
#define WT    (WUP / TT)         // 1 warmup tile
#define NSTG  4                  // pipeline stages
#define STRD  36                 // smem row stride (floats)

__device__ __forceinline__ void cp_async16(uint32_t smem_dst, const void* gsrc) {
    asm volatile("cp.async.cg.shared.global [%0], [%1], 16;\n"
                 :: "r"(smem_dst), "l"(gsrc));
}
__device__ __forceinline__ void cp_commit() {
    asm volatile("cp.async.commit_group;\n");
}
template <int N>
__device__ __forceinline__ void cp_wait() {
    asm volatile("cp.async.wait_group %0;\n" :: "n"(N));
}

__device__ __forceinline__ float spike_of(float z) {
    // s = (z >= 0) ? 1.0f : 0.0f via sign bit (z == -0 cannot occur here)
    int zb = __float_as_int(z);
    return __int_as_float(0x3f800000 & ~(zb >> 31));
}

__global__ __launch_bounds__(NTHR) void lif_kernel(const float* __restrict__ I,
                                                   float* __restrict__ Z,
                                                   float* __restrict__ S) {
    __shared__ __align__(16) float sI[NSTG][BR][STRD];

    const int tid     = threadIdx.x;
    const int lane    = tid & 31;
    const int isStore = tid >> 5;                   // warp 1 = store warp

    const int chunk    = blockIdx.x & (CH - 1);
    const int rowBlk   = blockIdx.x >> 2;           // CH == 4
    const long rowBase = (long)rowBlk * BR;

    const int startT    = chunk * CHL - (chunk ? WUP : 0);
    const int numTiles  = chunk ? (WT + MT) : MT;
    const int storeFrom = chunk ? WT : 0;

    // alpha = float(exp(-DT/TAU)) = float(exp(-1/3))
    const float alpha = 0.71653131057378925043f;
    const float omal  = 1.0f - alpha;
    const float thr   = 0.25f;
    const float beta  = 10.0f;
    const float nbt   = -beta * thr;     // -2.5f

    float v = 0.0f;

    const long chunkBase = rowBase * L_DIM + startT;

    // Tile slice mapping (both warps): e4 = k*32 + lane ; r = e4/8 ;
    // c4 = (e4%8)*4 -> 8 consecutive lanes cover a row's 128B (full line).

    if (!isStore) {
        // ---- prologue: issue tiles 0 and 1 into stages 0,1 ----
        #pragma unroll
        for (int p = 0; p < 2; ++p) {
            const float* gb = I + chunkBase + p * TT;
            #pragma unroll
            for (int k = 0; k < 8; ++k) {
                int e4 = k * BR + lane;
                int r  = e4 >> 3;
                int c4 = (e4 & 7) << 2;
                uint32_t dst = (uint32_t)__cvta_generic_to_shared(&sI[p][r][c4]);
                cp_async16(dst, gb + (long)r * L_DIM + c4);
            }
            cp_commit();
        }
    }

    #pragma unroll 1
    for (int tile = 0; tile < numTiles; ++tile) {
        // Cross-warp invariant: warp1 finished stores of tiles <= tile-2, so
        // stage (tile+2)&3 (held tile-2) is free for refill; stage (tile-1)&3
        // holds warp0's scanned z of tile-1.
        __syncthreads();

        if (!isStore) {
            const long gbase = chunkBase + (long)tile * TT;

            if (tile + 2 < numTiles) {
                // ---- issue tile+2 into stage (tile+2)&3 ----
                const int  nxt = (tile + 2) & (NSTG - 1);
                const float* gb = I + gbase + 2 * TT;
                #pragma unroll
                for (int k = 0; k < 8; ++k) {
                    int e4 = k * BR + lane;
                    int r  = e4 >> 3;
                    int c4 = (e4 & 7) << 2;
                    uint32_t dst = (uint32_t)__cvta_generic_to_shared(&sI[nxt][r][c4]);
                    cp_async16(dst, gb + (long)r * L_DIM + c4);
                }
                cp_commit();
                cp_wait<2>();           // oldest pending (this tile) landed
            } else if (tile + 1 < numTiles) {
                cp_wait<1>();
            } else {
                cp_wait<0>();
            }
            __syncwarp();

            const int cur = tile & (NSTG - 1);
            const bool doStore = (tile >= storeFrom);

            // ---- sequential scan of TT steps; z written back in place ----
            #pragma unroll
            for (int c = 0; c < TT; c += 4) {
                float4 i4 = *reinterpret_cast<const float4*>(&sI[cur][lane][c]);
                float4 z4;
                float vp;
                vp = fmaf(alpha, v, __fmul_rn(omal, i4.x));
                z4.x = fmaf(beta, vp, nbt);
                v = (vp >= thr) ? 0.0f : vp;
                vp = fmaf(alpha, v, __fmul_rn(omal, i4.y));
                z4.y = fmaf(beta, vp, nbt);
                v = (vp >= thr) ? 0.0f : vp;
                vp = fmaf(alpha, v, __fmul_rn(omal, i4.z));
                z4.z = fmaf(beta, vp, nbt);
                v = (vp >= thr) ? 0.0f : vp;
                vp = fmaf(alpha, v, __fmul_rn(omal, i4.w));
                z4.w = fmaf(beta, vp, nbt);
                v = (vp >= thr) ? 0.0f : vp;
                if (doStore)
                    *reinterpret_cast<float4*>(&sI[cur][lane][c]) = z4;
            }
        } else {
            // ---- store warp: stream tile-1 (scanned last iteration) ----
            const int j = tile - 1;
            if (j >= storeFrom) {
                const int  stg    = j & (NSTG - 1);
                const long gbaseJ = chunkBase + (long)j * TT;
                // Z burst: 8 x STG.128, one contiguous region per row-block
                #pragma unroll
                for (int k = 0; k < 8; ++k) {
                    int e4 = k * BR + lane;
                    int r  = e4 >> 3;
                    int c4 = (e4 & 7) << 2;
                    float4 z4 = *reinterpret_cast<const float4*>(&sI[stg][r][c4]);
                    *reinterpret_cast<float4*>(&Z[gbaseJ + (long)r * L_DIM + c4]) = z4;
                }
                // S burst: 8 x STG.128
                #pragma unroll
                for (int k = 0; k < 8; ++k) {
                    int e4 = k * BR + lane;
                    int r  = e4 >> 3;
                    int c4 = (e4 & 7) << 2;
                    float4 z4 = *reinterpret_cast<const float4*>(&sI[stg][r][c4]);
                    float4 s4;
                    s4.x = spike_of(z4.x);
                    s4.y = spike_of(z4.y);
                    s4.z = spike_of(z4.z);
                    s4.w = spike_of(z4.w);
                    *reinterpret_cast<float4*>(&S[gbaseJ + (long)r * L_DIM + c4]) = s4;
                }
            }
        }
    }

    // ---- epilogue: store the final tile ----
    __syncthreads();
    if (isStore) {
        const int  j      = numTiles - 1;
        const int  stg    = j & (NSTG - 1);
        const long gbaseJ = chunkBase + (long)j * TT;
        #pragma unroll
        for (int k = 0; k < 8; ++k) {
            int e4 = k * BR + lane;
            int r  = e4 >> 3;
            int c4 = (e4 & 7) << 2;
            float4 z4 = *reinterpret_cast<const float4*>(&sI[stg][r][c4]);
            *reinterpret_cast<float4*>(&Z[gbaseJ + (long)r * L_DIM + c4]) = z4;
        }
        #pragma unroll
        for (int k = 0; k < 8; ++k) {
            int e4 = k * BR + lane;
            int r  = e4 >> 3;
            int c4 = (e4 & 7) << 2;
            float4 z4 = *reinterpret_cast<const float4*>(&sI[stg][r][c4]);
            float4 s4;
            s4.x = spike_of(z4.x);
            s4.y = spike_of(z4.y);
            s4.z = spike_of(z4.z);
            s4.w = spike_of(z4.w);
            *reinterpret_cast<float4*>(&S[gbaseJ + (long)r * L_DIM + c4]) = s4;
        }
    }
}

extern "C" void kernel_launch(void* const* d_in, const int* in_sizes, int n_in,
                              void* d_out, int out_size) {
    const float* I = (const float*)d_in[0];
    float* out = (float*)d_out;
    const int n    = in_sizes[0];        // B*F*L = 33554432
    const int rows = n / L_DIM;          // 32768
    float* Z = out;                      // z history first
    float* S = out + n;                  // then s history
    lif_kernel<<<(rows / BR) * CH, NTHR>>>(I, Z, S);
}